// round 1
// baseline (speedup 1.0000x reference)
#include <cuda_runtime.h>

#define BB 64
#define TT 1024
#define EE 256
#define CIN 8
#define OO 63
#define NROWS (BB*TT)          // 65536 (b,t) rows
#define W_STRIDE (EE*3)        // 768 floats per output channel

// ---------------- scratch (device globals; no allocation allowed) ----------
__device__ float g_Y[BB*TT*EE];        // conv output, layout [b][t][e]
__device__ float g_S[BB*TT*EE];        // spikes (0/1 fp32), layout [b][t][e]
__device__ float g_part[256][2*EE];    // per-block partial (sum, sumsq)
__device__ float g_sum[EE];
__device__ float g_sumsq[EE];
__device__ float g_mean[BB*EE];        // temporal mean of last block spikes

// ---------------- f32x2 helpers -------------------------------------------
__device__ __forceinline__ unsigned long long pack2(float lo, float hi) {
    unsigned long long r;
    asm("mov.b64 %0, {%1, %2};" : "=l"(r) : "f"(lo), "f"(hi));
    return r;
}
__device__ __forceinline__ void fma2(unsigned long long& d,
                                     unsigned long long a,
                                     unsigned long long b) {
    asm("fma.rn.f32x2 %0, %1, %2, %0;" : "+l"(d) : "l"(a), "l"(b));
}
__device__ __forceinline__ float2 unpack2(unsigned long long v) {
    float2 f;
    asm("mov.b64 {%0, %1}, %2;" : "=f"(f.x), "=f"(f.y) : "l"(v));
    return f;
}

// ---------------- conv0: x[B,T,8] -> Y[B,T,E] ------------------------------
__global__ void conv0_kernel(const float* __restrict__ x,
                             const float* __restrict__ w,
                             const float* __restrict__ bias) {
    const int e = threadIdx.x;          // 0..255
    const int bt = blockIdx.x;          // 0..65535
    const int t = bt & (TT - 1);
    const int b = bt >> 10;
    float acc = bias[e];
    const float* wr = w + e * (CIN * 3);
    #pragma unroll
    for (int k = 0; k < 3; ++k) {
        const int gt = t + k - 1;
        if ((unsigned)gt < TT) {
            const float* xr = x + (b * TT + gt) * CIN;
            #pragma unroll
            for (int ci = 0; ci < CIN; ++ci)
                acc += xr[ci] * wr[ci * 3 + k];
        }
    }
    g_Y[(b * TT + t) * EE + e] = acc;
}

// ---------------- E->E conv1d (k=3) tiled, FFMA2 ---------------------------
// Tile: 64 e  x 64 t per block, one b. 256 threads: tx(e-group) x ty(t-group),
// each thread computes 4e x 4t outputs. c processed in chunks of 32.
__global__ __launch_bounds__(256) void conv_ee_kernel(const float* __restrict__ W,
                                                      const float* __restrict__ bias) {
    __shared__ __align__(16) float ws[96 * 68 + 4];   // [ck = c*3+k][e], stride 68
    __shared__ __align__(16) float ss[32 * 67 + 4];   // [c][trow], trow 0..65 (t0-1..t0+64)

    const int tid = threadIdx.x;
    const int tx = tid & 15;       // e group
    const int ty = tid >> 4;       // t group
    const int t0 = blockIdx.x * 64;
    const int e0 = blockIdx.y * 64;
    const int b  = blockIdx.z;
    const int tb = ty * 4;
    const int eb = tx * 4;

    unsigned long long acc[4][2];  // [t][e-pair]
    #pragma unroll
    for (int j = 0; j < 4; ++j) { acc[j][0] = 0ull; acc[j][1] = 0ull; }

    for (int c0 = 0; c0 < EE; c0 += 32) {
        __syncthreads();
        // load weights: 64e x 32c x 3k = 6144 floats, global-contiguous per e row
        #pragma unroll 4
        for (int i = tid; i < 6144; i += 256) {
            const int e  = i / 96;
            const int ck = i - e * 96;
            ws[ck * 68 + e] = W[(e0 + e) * W_STRIDE + c0 * 3 + ck];
        }
        // load spikes: 66 rows x 32 c
        #pragma unroll 4
        for (int i = tid; i < 66 * 32; i += 256) {
            const int trow = i >> 5;
            const int cc   = i & 31;
            const int gt   = t0 - 1 + trow;
            float v = 0.f;
            if ((unsigned)gt < TT) v = g_S[((b << 10) + gt) * EE + c0 + cc];
            ss[cc * 67 + trow] = v;
        }
        __syncthreads();

        #pragma unroll 4
        for (int c = 0; c < 32; ++c) {
            const float* sp = ss + c * 67 + tb;
            float sv[6];
            #pragma unroll
            for (int i = 0; i < 6; ++i) sv[i] = sp[i];
            unsigned long long sd[6];
            #pragma unroll
            for (int i = 0; i < 6; ++i) sd[i] = pack2(sv[i], sv[i]);

            const float* wp = ws + (c * 3) * 68 + eb;
            ulonglong2 wv[3];
            #pragma unroll
            for (int k = 0; k < 3; ++k)
                wv[k] = *reinterpret_cast<const ulonglong2*>(wp + k * 68);

            #pragma unroll
            for (int j = 0; j < 4; ++j) {
                #pragma unroll
                for (int k = 0; k < 3; ++k) {
                    fma2(acc[j][0], wv[k].x, sd[j + k]);
                    fma2(acc[j][1], wv[k].y, sd[j + k]);
                }
            }
        }
    }

    // epilogue: add bias, store float4 per t-row
    const float4 b4 = *reinterpret_cast<const float4*>(bias + e0 + eb);
    float* out = g_Y + ((b << 10) + t0 + tb) * EE + e0 + eb;
    #pragma unroll
    for (int j = 0; j < 4; ++j) {
        const float2 lo = unpack2(acc[j][0]);
        const float2 hi = unpack2(acc[j][1]);
        float4 o;
        o.x = lo.x + b4.x; o.y = lo.y + b4.y;
        o.z = hi.x + b4.z; o.w = hi.y + b4.w;
        *reinterpret_cast<float4*>(out + j * EE) = o;
    }
}

// ---------------- BN stats: deterministic two-stage ------------------------
__global__ void stats_kernel() {
    const int e  = threadIdx.x;
    const int r0 = blockIdx.x * 256;
    float s = 0.f, s2 = 0.f;
    const float* p = g_Y + (size_t)r0 * EE + e;
    #pragma unroll 8
    for (int r = 0; r < 256; ++r) {
        const float v = p[(size_t)r * EE];
        s += v;
        s2 += v * v;
    }
    g_part[blockIdx.x][e]      = s;
    g_part[blockIdx.x][EE + e] = s2;
}

__global__ void reduce_stats_kernel() {
    const int e = threadIdx.x;
    float s = 0.f, s2 = 0.f;
    #pragma unroll 8
    for (int j = 0; j < 256; ++j) {
        s  += g_part[j][e];
        s2 += g_part[j][EE + e];
    }
    g_sum[e]   = s;
    g_sumsq[e] = s2;
}

// ---------------- BN normalize + LIF scan over T ---------------------------
__global__ void lif_kernel(const float* __restrict__ gamma,
                           const float* __restrict__ beta,
                           int storeS, int doMean) {
    const int tid = blockIdx.x * blockDim.x + threadIdx.x;  // 0..16383
    const int e = tid & (EE - 1);
    const int b = tid >> 8;

    const float mu   = g_sum[e] * (1.f / (float)NROWS);
    const float var  = g_sumsq[e] * (1.f / (float)NROWS) - mu * mu;
    const float rstd = 1.f / sqrtf(var + 1e-5f);
    const float a = rstd * gamma[e];
    const float c = beta[e] - mu * a;

    const float* yp = g_Y + (size_t)b * TT * EE + e;
    float* sp       = g_S + (size_t)b * TT * EE + e;

    float v = 0.f, cnt = 0.f;
    #pragma unroll 16
    for (int t = 0; t < TT; ++t) {
        const float xn = fmaf(yp[(size_t)t * EE], a, c);
        v = v + (xn - v) * 0.5f;            // LIF charge, TAU = 2
        const float s = (v >= 1.0f) ? 1.0f : 0.0f;
        if (storeS) sp[(size_t)t * EE] = s;
        cnt += s;
        v = (v >= 1.0f) ? 0.0f : v;         // detached hard reset
    }
    if (doMean) g_mean[tid] = cnt * (1.f / (float)TT);
}

// ---------------- head: [B,E] @ [O,E]^T + b --------------------------------
__global__ void head_kernel(const float* __restrict__ hw,
                            const float* __restrict__ hb,
                            float* __restrict__ out) {
    const int b = blockIdx.x;
    const int o = threadIdx.x;
    if (o >= OO) return;
    float acc = hb[o];
    const float* mp = g_mean + b * EE;
    const float* wr = hw + o * EE;
    #pragma unroll 8
    for (int e = 0; e < EE; ++e) acc += mp[e] * wr[e];
    out[b * OO + o] = acc;
}

// ---------------- launch ----------------------------------------------------
extern "C" void kernel_launch(void* const* d_in, const int* in_sizes, int n_in,
                              void* d_out, int out_size) {
    const float* x     = (const float*)d_in[0];
    const float* w0    = (const float*)d_in[1];
    const float* b0    = (const float*)d_in[2];
    const float* wc    = (const float*)d_in[3];   // [3,E,E,3]
    const float* bc    = (const float*)d_in[4];   // [3,E]
    const float* gamma = (const float*)d_in[5];   // [4,E]
    const float* beta  = (const float*)d_in[6];   // [4,E]
    const float* hw    = (const float*)d_in[7];   // [O,E]
    const float* hb    = (const float*)d_in[8];   // [O]
    float* out = (float*)d_out;

    // block 0
    conv0_kernel<<<NROWS, EE>>>(x, w0, b0);
    stats_kernel<<<256, 256>>>();
    reduce_stats_kernel<<<1, 256>>>();
    lif_kernel<<<64, 256>>>(gamma, beta, 1, 0);

    // blocks 1..3
    for (int i = 0; i < 3; ++i) {
        conv_ee_kernel<<<dim3(16, 4, BB), 256>>>(wc + (size_t)i * EE * EE * 3,
                                                 bc + i * EE);
        stats_kernel<<<256, 256>>>();
        reduce_stats_kernel<<<1, 256>>>();
        const int last = (i == 2);
        lif_kernel<<<64, 256>>>(gamma + (i + 1) * EE, beta + (i + 1) * EE,
                                !last, last);
    }

    head_kernel<<<BB, 64>>>(hw, hb, out);
}

// round 2
// speedup vs baseline: 1.7084x; 1.7084x over previous
#include <cuda_runtime.h>

#define BB 64
#define TT 1024
#define EE 256
#define CIN 8
#define OO 63
#define NROWS (BB*TT)          // 65536
#define W_STRIDE (EE*3)

// ---------------- scratch (device globals) ---------------------------------
// layout [b][e][t]
__device__ float g_Y[(size_t)BB*EE*TT];
__device__ float g_S[(size_t)BB*EE*TT];
__device__ float g_sum[EE];
__device__ float g_sumsq[EE];
__device__ float g_mean[BB*EE];

// ---------------- f32x2 helpers -------------------------------------------
__device__ __forceinline__ unsigned long long pack2(float lo, float hi) {
    unsigned long long r;
    asm("mov.b64 %0, {%1, %2};" : "=l"(r) : "f"(lo), "f"(hi));
    return r;
}
__device__ __forceinline__ void fma2(unsigned long long& d,
                                     unsigned long long a,
                                     unsigned long long b) {
    asm("fma.rn.f32x2 %0, %1, %2, %0;" : "+l"(d) : "l"(a), "l"(b));
}
__device__ __forceinline__ float2 unpack2(unsigned long long v) {
    float2 f;
    asm("mov.b64 {%0, %1}, %2;" : "=f"(f.x), "=f"(f.y) : "l"(v));
    return f;
}

// ---------------- conv0: x[B,T,8] -> Y[b][e][t] -----------------------------
// block = (tchunk, b); 256 threads; smem x-tile + all weights in smem.
__global__ __launch_bounds__(256) void conv0_kernel(const float* __restrict__ x,
                                                    const float* __restrict__ w,
                                                    const float* __restrict__ bias) {
    __shared__ float xs[258 * 8];          // rows t0-1 .. t0+256
    __shared__ float ws[EE * 24];
    __shared__ float bs[EE];
    const int tid = threadIdx.x;
    const int t0 = blockIdx.x * 256;
    const int b  = blockIdx.y;

    #pragma unroll 4
    for (int i = tid; i < EE * 24; i += 256) ws[i] = w[i];
    bs[tid] = bias[tid];
    #pragma unroll 4
    for (int i = tid; i < 258 * 8; i += 256) {
        const int r = i >> 3, c = i & 7;
        const int gt = t0 - 1 + r;
        xs[i] = ((unsigned)gt < TT) ? x[(b * TT + gt) * CIN + c] : 0.f;
    }
    __syncthreads();

    for (int e = 0; e < EE; ++e) {
        const float* we = ws + e * 24;
        float acc = bs[e];
        #pragma unroll
        for (int c = 0; c < CIN; ++c)
            #pragma unroll
            for (int k = 0; k < 3; ++k)
                acc += xs[(tid + k) * 8 + c] * we[c * 3 + k];
        g_Y[((size_t)b * EE + e) * TT + t0 + tid] = acc;
    }
}

// ---------------- E->E conv1d (k=3) tiled, FFMA2, [b][e][t] -----------------
__global__ __launch_bounds__(256) void conv_ee_kernel(const float* __restrict__ W,
                                                      const float* __restrict__ bias) {
    __shared__ __align__(16) float ws[96 * 68 + 4];   // [c*3+k][e], stride 68
    __shared__ __align__(16) float ss[32 * 67 + 4];   // [c][trow], trow 0..65

    const int tid = threadIdx.x;
    const int tx = tid & 15;       // e group
    const int ty = tid >> 4;       // t group
    const int t0 = blockIdx.x * 64;
    const int e0 = blockIdx.y * 64;
    const int b  = blockIdx.z;
    const int tb = ty * 4;
    const int eb = tx * 4;

    unsigned long long acc[4][2];
    #pragma unroll
    for (int j = 0; j < 4; ++j) { acc[j][0] = 0ull; acc[j][1] = 0ull; }

    for (int c0 = 0; c0 < EE; c0 += 32) {
        __syncthreads();
        #pragma unroll 4
        for (int i = tid; i < 6144; i += 256) {
            const int e  = i / 96;
            const int ck = i - e * 96;
            ws[ck * 68 + e] = W[(e0 + e) * W_STRIDE + c0 * 3 + ck];
        }
        #pragma unroll 4
        for (int i = tid; i < 32 * 66; i += 256) {
            const int c    = i / 66;
            const int trow = i - c * 66;
            const int gt   = t0 - 1 + trow;
            float v = 0.f;
            if ((unsigned)gt < TT)
                v = g_S[((size_t)b * EE + c0 + c) * TT + gt];
            ss[c * 67 + trow] = v;
        }
        __syncthreads();

        #pragma unroll 4
        for (int c = 0; c < 32; ++c) {
            const float* sp = ss + c * 67 + tb;
            float sv[6];
            #pragma unroll
            for (int i = 0; i < 6; ++i) sv[i] = sp[i];
            unsigned long long sd[6];
            #pragma unroll
            for (int i = 0; i < 6; ++i) sd[i] = pack2(sv[i], sv[i]);

            const float* wp = ws + (c * 3) * 68 + eb;
            ulonglong2 wv[3];
            #pragma unroll
            for (int k = 0; k < 3; ++k)
                wv[k] = *reinterpret_cast<const ulonglong2*>(wp + k * 68);

            #pragma unroll
            for (int j = 0; j < 4; ++j) {
                #pragma unroll
                for (int k = 0; k < 3; ++k) {
                    fma2(acc[j][0], wv[k].x, sd[j + k]);
                    fma2(acc[j][1], wv[k].y, sd[j + k]);
                }
            }
        }
    }

    // epilogue: [e][t] float4 stores over t
    float va[4][4];
    #pragma unroll
    for (int j = 0; j < 4; ++j) {
        const float2 lo = unpack2(acc[j][0]);
        const float2 hi = unpack2(acc[j][1]);
        va[j][0] = lo.x; va[j][1] = lo.y; va[j][2] = hi.x; va[j][3] = hi.y;
    }
    #pragma unroll
    for (int i = 0; i < 4; ++i) {
        const int ge = e0 + eb + i;
        const float bv = bias[ge];
        float4 o;
        o.x = va[0][i] + bv; o.y = va[1][i] + bv;
        o.z = va[2][i] + bv; o.w = va[3][i] + bv;
        *reinterpret_cast<float4*>(g_Y + ((size_t)b * EE + ge) * TT + t0 + tb) = o;
    }
}

// ---------------- BN stats: one block per channel, deterministic tree -------
__global__ __launch_bounds__(256) void stats_kernel() {
    __shared__ float rs[256], rs2[256];
    const int e = blockIdx.x;
    const int tid = threadIdx.x;
    const int b = tid >> 2;
    const int q = tid & 3;
    const float4* p = (const float4*)(g_Y + ((size_t)b * EE + e) * TT + q * 256);
    float s = 0.f, s2 = 0.f;
    #pragma unroll 8
    for (int r = 0; r < 64; ++r) {
        const float4 f = p[r];
        s += f.x; s2 += f.x * f.x;
        s += f.y; s2 += f.y * f.y;
        s += f.z; s2 += f.z * f.z;
        s += f.w; s2 += f.w * f.w;
    }
    rs[tid] = s; rs2[tid] = s2;
    __syncthreads();
    #pragma unroll
    for (int w = 128; w > 0; w >>= 1) {
        if (tid < w) { rs[tid] += rs[tid + w]; rs2[tid] += rs2[tid + w]; }
        __syncthreads();
    }
    if (tid == 0) { g_sum[e] = rs[0]; g_sumsq[e] = rs2[0]; }
}

// ---------------- BN normalize + LIF scan, streaming float4 -----------------
__global__ __launch_bounds__(64) void lif_kernel(const float* __restrict__ gamma,
                                                 const float* __restrict__ beta,
                                                 int storeS, int doMean) {
    const int e = blockIdx.x * 64 + threadIdx.x;
    const int b = blockIdx.y;

    const float mu   = g_sum[e] * (1.f / (float)NROWS);
    const float var  = g_sumsq[e] * (1.f / (float)NROWS) - mu * mu;
    const float rstd = 1.f / sqrtf(var + 1e-5f);
    const float a = rstd * gamma[e];
    const float c = beta[e] - mu * a;

    const float4* yv = (const float4*)(g_Y + ((size_t)b * EE + e) * TT);
    float4* sv       = (float4*)(g_S + ((size_t)b * EE + e) * TT);

    float v = 0.f, cnt = 0.f;
    float4 nb[4];
    #pragma unroll
    for (int i = 0; i < 4; ++i) nb[i] = yv[i];

    for (int base = 0; base < 256; base += 4) {
        float4 cur[4];
        #pragma unroll
        for (int i = 0; i < 4; ++i) cur[i] = nb[i];
        if (base + 4 < 256) {
            #pragma unroll
            for (int i = 0; i < 4; ++i) nb[i] = yv[base + 4 + i];
        }
        #pragma unroll
        for (int i = 0; i < 4; ++i) {
            float in[4] = {cur[i].x, cur[i].y, cur[i].z, cur[i].w};
            float o[4];
            #pragma unroll
            for (int j = 0; j < 4; ++j) {
                const float xn = fmaf(in[j], a, c);
                v = v + (xn - v) * 0.5f;
                const float s = (v >= 1.0f) ? 1.0f : 0.0f;
                cnt += s;
                v = (v >= 1.0f) ? 0.0f : v;
                o[j] = s;
            }
            if (storeS) sv[base + i] = make_float4(o[0], o[1], o[2], o[3]);
        }
    }
    if (doMean) g_mean[b * EE + e] = cnt * (1.f / (float)TT);
}

// ---------------- head ------------------------------------------------------
__global__ void head_kernel(const float* __restrict__ hw,
                            const float* __restrict__ hb,
                            float* __restrict__ out) {
    const int b = blockIdx.x;
    const int o = threadIdx.x;
    if (o >= OO) return;
    float acc = hb[o];
    const float* mp = g_mean + b * EE;
    const float* wr = hw + o * EE;
    #pragma unroll 8
    for (int e = 0; e < EE; ++e) acc += mp[e] * wr[e];
    out[b * OO + o] = acc;
}

// ---------------- launch ----------------------------------------------------
extern "C" void kernel_launch(void* const* d_in, const int* in_sizes, int n_in,
                              void* d_out, int out_size) {
    const float* x     = (const float*)d_in[0];
    const float* w0    = (const float*)d_in[1];
    const float* b0    = (const float*)d_in[2];
    const float* wc    = (const float*)d_in[3];
    const float* bc    = (const float*)d_in[4];
    const float* gamma = (const float*)d_in[5];
    const float* beta  = (const float*)d_in[6];
    const float* hw    = (const float*)d_in[7];
    const float* hb    = (const float*)d_in[8];
    float* out = (float*)d_out;

    conv0_kernel<<<dim3(4, BB), 256>>>(x, w0, b0);
    stats_kernel<<<EE, 256>>>();
    lif_kernel<<<dim3(4, BB), 64>>>(gamma, beta, 1, 0);

    for (int i = 0; i < 3; ++i) {
        conv_ee_kernel<<<dim3(16, 4, BB), 256>>>(wc + (size_t)i * EE * EE * 3,
                                                 bc + i * EE);
        stats_kernel<<<EE, 256>>>();
        const int last = (i == 2);
        lif_kernel<<<dim3(4, BB), 64>>>(gamma + (i + 1) * EE, beta + (i + 1) * EE,
                                        !last, last);
    }

    head_kernel<<<BB, 64>>>(hw, hb, out);
}

// round 6
// speedup vs baseline: 5.2873x; 3.0948x over previous
#include <cuda_runtime.h>
#include <cuda_bf16.h>
#include <cstdint>

#define BB 64
#define TT 1024
#define EE 256
#define CIN 8
#define OO 63
#define NROWS (BB*TT)
#define KK 768                    // im2col K = 3 k * 256 c, index = k*256+c

// ---------------- scratch (device globals) ---------------------------------
__device__ __align__(16) float g_Y[(size_t)BB*EE*TT];            // [b][e][t]
__device__ __align__(16) __nv_bfloat16 g_B[(size_t)BB*TT*KK];    // [b][t'][k*256+c]
__device__ __align__(16) __nv_bfloat16 g_Whi[3*EE*KK];           // [conv][e][k*256+c]
__device__ __align__(16) __nv_bfloat16 g_Wlo[3*EE*KK];
__device__ float g_sum[EE];
__device__ float g_sumsq[EE];
__device__ float g_mean[BB*EE];

// ---------------- PTX helpers ----------------------------------------------
__device__ __forceinline__ uint32_t smem_u32(const void* p) {
    uint32_t a;
    asm("{ .reg .u64 t; cvta.to.shared.u64 t, %1; cvt.u32.u64 %0, t; }" : "=r"(a) : "l"(p));
    return a;
}
__device__ __forceinline__ void cpasync16(uint32_t dst, const void* src) {
    asm volatile("cp.async.cg.shared.global [%0], [%1], 16;" :: "r"(dst), "l"(src) : "memory");
}
#define CP_COMMIT() asm volatile("cp.async.commit_group;" ::: "memory")
#define CP_WAIT(n)  asm volatile("cp.async.wait_group %0;" :: "n"(n) : "memory")

__device__ __forceinline__ void ldmx4(uint32_t* r, uint32_t addr) {
    asm volatile("ldmatrix.sync.aligned.m8n8.x4.shared.b16 {%0,%1,%2,%3}, [%4];"
                 : "=r"(r[0]), "=r"(r[1]), "=r"(r[2]), "=r"(r[3]) : "r"(addr));
}
__device__ __forceinline__ void mma_bf16(float* d, const uint32_t* a, const uint32_t* b) {
    asm volatile("mma.sync.aligned.m16n8k16.row.col.f32.bf16.bf16.f32 "
                 "{%0,%1,%2,%3}, {%4,%5,%6,%7}, {%8,%9}, {%0,%1,%2,%3};"
                 : "+f"(d[0]), "+f"(d[1]), "+f"(d[2]), "+f"(d[3])
                 : "r"(a[0]), "r"(a[1]), "r"(a[2]), "r"(a[3]), "r"(b[0]), "r"(b[1]));
}

// ---------------- weight split + permute: W[e][c][k] -> [e][k*256+c] --------
__global__ void split_w_kernel(const float* __restrict__ wc) {
    const int i = blockIdx.x * blockDim.x + threadIdx.x;
    if (i >= 3 * EE * KK) return;
    const int conv = i / (EE * KK);
    const int r    = i - conv * EE * KK;
    const int e    = r / KK;
    const int kc   = r - e * KK;
    const int k    = kc >> 8;          // 0..2
    const int c    = kc & 255;
    const float w = wc[((conv * EE + e) * EE + c) * 3 + k];
    const __nv_bfloat16 hi = __float2bfloat16(w);
    g_Whi[i] = hi;
    g_Wlo[i] = __float2bfloat16(w - __bfloat162float(hi));
}

// ---------------- conv0: x[B,T,8] -> Y[b][e][t] -----------------------------
__global__ __launch_bounds__(256) void conv0_kernel(const float* __restrict__ x,
                                                    const float* __restrict__ w,
                                                    const float* __restrict__ bias) {
    __shared__ float xs[258 * 8];
    __shared__ float ws[EE * 24];
    __shared__ float bs[EE];
    const int tid = threadIdx.x;
    const int t0 = blockIdx.x * 256;
    const int b  = blockIdx.y;

    #pragma unroll 4
    for (int i = tid; i < EE * 24; i += 256) ws[i] = w[i];
    bs[tid] = bias[tid];
    #pragma unroll 4
    for (int i = tid; i < 258 * 8; i += 256) {
        const int r = i >> 3, c = i & 7;
        const int gt = t0 - 1 + r;
        xs[i] = ((unsigned)gt < TT) ? x[(b * TT + gt) * CIN + c] : 0.f;
    }
    __syncthreads();

    for (int e = 0; e < EE; ++e) {
        const float* we = ws + e * 24;
        float acc = bs[e];
        #pragma unroll
        for (int c = 0; c < CIN; ++c)
            #pragma unroll
            for (int k = 0; k < 3; ++k)
                acc += xs[(tid + k) * 8 + c] * we[c * 3 + k];
        g_Y[((size_t)b * EE + e) * TT + t0 + tid] = acc;
    }
}

// ---------------- mma.sync conv GEMM: Y[e][t] = (Whi+Wlo)[e][K] . B[t][K] ---
#define KC 32
#define NCH 24                     // 768 / 32
#define NSTAGE 4
#define MATB (128 * KC * 2)        // 8 KB per matrix tile
#define STAGEB (3 * MATB)          // 24 KB per stage (Ahi, Alo, B)

__global__ __launch_bounds__(256, 2) void conv_mma_kernel(const float* __restrict__ bias,
                                                          int conv_idx) {
    extern __shared__ char dsm[];
    const uint32_t sb = smem_u32(dsm);
    const int tid  = threadIdx.x;
    const int lane = tid & 31;
    const int wid  = tid >> 5;
    const int warp_m = wid & 3;         // 32-e slice
    const int warp_n = wid >> 2;        // 64-t slice
    const int t0 = blockIdx.x * 128;
    const int e0 = blockIdx.y * 128;
    const int b  = blockIdx.z;

    const __nv_bfloat16* Ahi  = g_Whi + (size_t)conv_idx * EE * KK + (size_t)e0 * KK;
    const __nv_bfloat16* Alo  = g_Wlo + (size_t)conv_idx * EE * KK + (size_t)e0 * KK;
    const __nv_bfloat16* Bsrc = g_B + ((size_t)b * TT + t0) * KK;

    const int l_row = tid >> 2;        // 0..63, second half row+64
    const int l_c   = tid & 3;         // 16B chunk within 64B row

    auto issue = [&](int ch) {
        const uint32_t stage = sb + (uint32_t)(ch & (NSTAGE - 1)) * STAGEB;
        const int k0 = ch * KC;
        #pragma unroll
        for (int it = 0; it < 2; ++it) {
            const int row = l_row + it * 64;
            const uint32_t soff = row * 64 + ((l_c ^ ((row >> 1) & 3)) << 4);
            const size_t goff = (size_t)row * KK + k0 + l_c * 8;
            cpasync16(stage + soff,            Ahi  + goff);
            cpasync16(stage + MATB + soff,     Alo  + goff);
            cpasync16(stage + 2 * MATB + soff, Bsrc + goff);
        }
    };

    float acc[2][8][4];
    #pragma unroll
    for (int mt = 0; mt < 2; ++mt)
        #pragma unroll
        for (int n = 0; n < 8; ++n)
            #pragma unroll
            for (int j = 0; j < 4; ++j) acc[mt][n][j] = 0.f;

    issue(0); CP_COMMIT();
    issue(1); CP_COMMIT();
    issue(2); CP_COMMIT();

    // per-lane ldmatrix row/chunk components (fixed across chunks)
    const int a_row_l = lane & 15;           // A: rows 0-15 of m16 tile
    const int a_cbit  = lane >> 4;           // A: k-lo / k-hi chunk
    const int b_row_l = (lane & 7) + ((lane & 16) >> 1);   // B: n row within 16
    const int b_cbit  = (lane >> 3) & 1;

    for (int ch = 0; ch < NCH; ++ch) {
        if (ch + NSTAGE - 1 < NCH) issue(ch + NSTAGE - 1);
        CP_COMMIT();
        CP_WAIT(NSTAGE - 2);
        __syncthreads();

        const uint32_t stage = sb + (uint32_t)(ch & (NSTAGE - 1)) * STAGEB;
        #pragma unroll
        for (int ks = 0; ks < 2; ++ks) {
            uint32_t ahi[2][4], alo[2][4], bfr[4][4];
            #pragma unroll
            for (int mt = 0; mt < 2; ++mt) {
                const int row = warp_m * 32 + mt * 16 + a_row_l;
                const int c   = ks * 2 + a_cbit;
                const uint32_t a = stage + row * 64 + ((c ^ ((row >> 1) & 3)) << 4);
                ldmx4(ahi[mt], a);
                ldmx4(alo[mt], a + MATB);
            }
            #pragma unroll
            for (int np = 0; np < 4; ++np) {
                const int row = warp_n * 64 + np * 16 + b_row_l;
                const int c   = ks * 2 + b_cbit;
                ldmx4(bfr[np], stage + 2 * MATB + row * 64 + ((c ^ ((row >> 1) & 3)) << 4));
            }
            #pragma unroll
            for (int mt = 0; mt < 2; ++mt)
                #pragma unroll
                for (int n = 0; n < 8; ++n) {
                    uint32_t bb[2] = { bfr[n >> 1][(n & 1) * 2],
                                       bfr[n >> 1][(n & 1) * 2 + 1] };
                    mma_bf16(acc[mt][n], ahi[mt], bb);
                    mma_bf16(acc[mt][n], alo[mt], bb);
                }
        }
        __syncthreads();
    }

    // epilogue: add bias, write g_Y[b][e][t]
    const int gq = lane >> 2;
    const int tc = lane & 3;
    #pragma unroll
    for (int mt = 0; mt < 2; ++mt) {
        #pragma unroll
        for (int half = 0; half < 2; ++half) {
            const int e = e0 + warp_m * 32 + mt * 16 + gq + half * 8;
            const float bv = bias[e];
            float* yp = g_Y + ((size_t)b * EE + e) * TT + t0 + warp_n * 64 + tc * 2;
            #pragma unroll
            for (int n = 0; n < 8; ++n) {
                float2 v;
                v.x = acc[mt][n][half * 2 + 0] + bv;
                v.y = acc[mt][n][half * 2 + 1] + bv;
                *reinterpret_cast<float2*>(yp + n * 8) = v;
            }
        }
    }
}

// ---------------- BN stats --------------------------------------------------
__global__ __launch_bounds__(256) void stats_kernel() {
    __shared__ float rs[256], rs2[256];
    const int e = blockIdx.x;
    const int tid = threadIdx.x;
    const int b = tid >> 2;
    const int q = tid & 3;
    const float4* p = (const float4*)(g_Y + ((size_t)b * EE + e) * TT + q * 256);
    float s = 0.f, s2 = 0.f;
    #pragma unroll 8
    for (int r = 0; r < 64; ++r) {
        const float4 f = p[r];
        s += f.x; s2 += f.x * f.x;
        s += f.y; s2 += f.y * f.y;
        s += f.z; s2 += f.z * f.z;
        s += f.w; s2 += f.w * f.w;
    }
    rs[tid] = s; rs2[tid] = s2;
    __syncthreads();
    #pragma unroll
    for (int w = 128; w > 0; w >>= 1) {
        if (tid < w) { rs[tid] += rs[tid + w]; rs2[tid] += rs2[tid + w]; }
        __syncthreads();
    }
    if (tid == 0) { g_sum[e] = rs[0]; g_sumsq[e] = rs2[0]; }
}

// ---------------- BN + LIF; spikes scattered into im2col B ------------------
__global__ __launch_bounds__(64) void lif_kernel(const float* __restrict__ gamma,
                                                 const float* __restrict__ beta,
                                                 int writeB, int doMean) {
    const int e = blockIdx.x * 64 + threadIdx.x;   // channel c
    const int b = blockIdx.y;

    const float mu   = g_sum[e] * (1.f / (float)NROWS);
    const float var  = g_sumsq[e] * (1.f / (float)NROWS) - mu * mu;
    const float rstd = 1.f / sqrtf(var + 1e-5f);
    const float a = rstd * gamma[e];
    const float c = beta[e] - mu * a;

    const float4* yv = (const float4*)(g_Y + ((size_t)b * EE + e) * TT);
    __nv_bfloat16* Bb = g_B + (size_t)b * TT * KK + e;   // c-slot = e
    const __nv_bfloat16 one  = __float2bfloat16(1.0f);
    const __nv_bfloat16 zero = __float2bfloat16(0.0f);

    if (writeB) {
        Bb[0] = zero;                          // t'=0,   k=0 (s[-1])
        Bb[(size_t)1023 * KK + 512] = zero;    // t'=1023,k=2 (s[1024])
    }

    float v = 0.f, cnt = 0.f;
    float4 nb[4];
    #pragma unroll
    for (int i = 0; i < 4; ++i) nb[i] = yv[i];

    for (int base = 0; base < 256; base += 4) {
        float4 cur[4];
        #pragma unroll
        for (int i = 0; i < 4; ++i) cur[i] = nb[i];
        if (base + 4 < 256) {
            #pragma unroll
            for (int i = 0; i < 4; ++i) nb[i] = yv[base + 4 + i];
        }
        #pragma unroll
        for (int i = 0; i < 4; ++i) {
            const int tB = (base + i) * 4;
            float in[4] = {cur[i].x, cur[i].y, cur[i].z, cur[i].w};
            #pragma unroll
            for (int j = 0; j < 4; ++j) {
                const int t = tB + j;
                const float xn = fmaf(in[j], a, c);
                v = v + (xn - v) * 0.5f;
                const float s = (v >= 1.0f) ? 1.0f : 0.0f;
                cnt += s;
                v = (v >= 1.0f) ? 0.0f : v;
                if (writeB) {
                    const __nv_bfloat16 sb = (s != 0.f) ? one : zero;
                    Bb[(size_t)t * KK + 256] = sb;                       // k=1
                    if (t + 1 < TT) Bb[(size_t)(t + 1) * KK] = sb;       // k=0
                    if (t >= 1)     Bb[(size_t)(t - 1) * KK + 512] = sb; // k=2
                }
            }
        }
    }
    if (doMean) g_mean[b * EE + e] = cnt * (1.f / (float)TT);
}

// ---------------- head ------------------------------------------------------
__global__ void head_kernel(const float* __restrict__ hw,
                            const float* __restrict__ hb,
                            float* __restrict__ out) {
    const int b = blockIdx.x;
    const int o = threadIdx.x;
    if (o >= OO) return;
    float acc = hb[o];
    const float* mp = g_mean + b * EE;
    const float* wr = hw + o * EE;
    #pragma unroll 8
    for (int e = 0; e < EE; ++e) acc += mp[e] * wr[e];
    out[b * OO + o] = acc;
}

// ---------------- launch ----------------------------------------------------
extern "C" void kernel_launch(void* const* d_in, const int* in_sizes, int n_in,
                              void* d_out, int out_size) {
    const float* x     = (const float*)d_in[0];
    const float* w0    = (const float*)d_in[1];
    const float* b0    = (const float*)d_in[2];
    const float* wc    = (const float*)d_in[3];
    const float* bc    = (const float*)d_in[4];
    const float* gamma = (const float*)d_in[5];
    const float* beta  = (const float*)d_in[6];
    const float* hw    = (const float*)d_in[7];
    const float* hb    = (const float*)d_in[8];
    float* out = (float*)d_out;

    const int SMEM_DYN = NSTAGE * STAGEB;   // 96 KB
    cudaFuncSetAttribute(conv_mma_kernel,
                         cudaFuncAttributeMaxDynamicSharedMemorySize, SMEM_DYN);

    split_w_kernel<<<(3 * EE * KK + 1023) / 1024, 1024>>>(wc);

    conv0_kernel<<<dim3(4, BB), 256>>>(x, w0, b0);
    stats_kernel<<<EE, 256>>>();
    lif_kernel<<<dim3(4, BB), 64>>>(gamma, beta, 1, 0);

    for (int i = 0; i < 3; ++i) {
        conv_mma_kernel<<<dim3(8, 2, BB), 256, SMEM_DYN>>>(bc + i * EE, i);
        stats_kernel<<<EE, 256>>>();
        const int last = (i == 2);
        lif_kernel<<<dim3(4, BB), 64>>>(gamma + (i + 1) * EE, beta + (i + 1) * EE,
                                        !last, last);
    }

    head_kernel<<<BB, 64>>>(hw, hb, out);
}